// round 1
// baseline (speedup 1.0000x reference)
#include <cuda_runtime.h>

// Problem constants
namespace {
constexpr int B = 2, N = 2048, F = 768, H = 8, O = 256, HO = H * O;
constexpr float ALPHA = 0.2f;
constexpr int TI = 64, TJ = 64;
constexpr int SMEM_ATTN = (TJ * O + TI * 65 + 4 * 64) * 4;  // 83200 bytes
}

// ---------------- scratch (static device globals; no allocation) ----------
__device__ float g_h  [(size_t)B * H * N * O];   // layer0 per-head features
__device__ float g_s1 [B * H * N];
__device__ float g_s2 [B * H * N];
__device__ float g_s2t[B * N * H];               // [b][n][h] for coalesced stats
__device__ float g_m  [B * H * N];
__device__ float g_rz [B * H * N];               // 1/Z
__device__ float g_x1 [(size_t)B * N * HO];      // concat(elu(att@h))
__device__ float g_h2 [(size_t)B * N * O];
__device__ float g_x2 [(size_t)B * N * O];       // lin + bias, then += att2@h2
__device__ float g_s1b[B * N];
__device__ float g_s2b[B * N];
__device__ float g_mb [B * N];
__device__ float g_rzb[B * N];

__device__ __forceinline__ float lrelu(float v) { return v > 0.f ? v : ALPHA * v; }
__device__ __forceinline__ float eluf(float v)  { return v > 0.f ? v : __expf(v) - 1.f; }

// ---------------- Kernel 1: h[b,h] = x[b] @ W_heads[h]  ([N,F]x[F,O]) -----
__global__ void k_gemm_h(const float* __restrict__ x, const float* __restrict__ Wh) {
    const int bh = blockIdx.z;
    const int b  = bh >> 3;
    const float* A  = x  + (size_t)b * N * F;
    const float* Bw = Wh + (size_t)(bh & 7) * F * O;
    float* C = g_h + (size_t)bh * N * O;
    const int i0 = blockIdx.y * 64;
    const int n0 = blockIdx.x * 64;
    __shared__ float As[16][64];
    __shared__ float Bs[16][64];
    const int tid  = threadIdx.x;
    const int tx   = tid & 15, ty = tid >> 4;
    const int arow = tid >> 2, acol = (tid & 3) << 2;
    const int brow = tid >> 4, bcol = (tid & 15) << 2;

    float acc[4][4] = {};
    for (int k0 = 0; k0 < F; k0 += 16) {
        float4 av = *(const float4*)(A + (size_t)(i0 + arow) * F + k0 + acol);
        As[acol + 0][arow] = av.x; As[acol + 1][arow] = av.y;
        As[acol + 2][arow] = av.z; As[acol + 3][arow] = av.w;
        *(float4*)&Bs[brow][bcol] =
            *(const float4*)(Bw + (size_t)(k0 + brow) * O + n0 + bcol);
        __syncthreads();
#pragma unroll
        for (int kk = 0; kk < 16; kk++) {
            const float4 bv = *(const float4*)&Bs[kk][tx << 2];
            const float bb[4] = {bv.x, bv.y, bv.z, bv.w};
#pragma unroll
            for (int r = 0; r < 4; r++) {
                const float a = As[kk][(ty << 2) + r];
#pragma unroll
                for (int c = 0; c < 4; c++) acc[r][c] += a * bb[c];
            }
        }
        __syncthreads();
    }
#pragma unroll
    for (int r = 0; r < 4; r++) {
        float4 v = {acc[r][0], acc[r][1], acc[r][2], acc[r][3]};
        *(float4*)(C + (size_t)(i0 + (ty << 2) + r) * O + n0 + (tx << 2)) = v;
    }
}

// ---------------- Kernel 2: s1/s2 dots (multi-head), warp per row ---------
__global__ void k_sdots_multi(const float* __restrict__ ah) {
    const int gt = blockIdx.x * 256 + threadIdx.x;
    const int gw = gt >> 5, lane = gt & 31;   // gw in [0, B*H*N)
    const int hh = (gw / N) & 7;
    const int b  = gw / (N * H);
    const int n  = gw % N;
    const float4* hr = (const float4*)(g_h + (size_t)gw * O);
    const float4* a1 = (const float4*)(ah + (size_t)hh * 2 * O);
    const float4* a2 = a1 + O / 4;
    float d1 = 0.f, d2 = 0.f;
#pragma unroll
    for (int t = 0; t < 2; t++) {
        const int idx = lane * 2 + t;
        const float4 hv = hr[idx], av = a1[idx], bv = a2[idx];
        d1 += hv.x * av.x + hv.y * av.y + hv.z * av.z + hv.w * av.w;
        d2 += hv.x * bv.x + hv.y * bv.y + hv.z * bv.z + hv.w * bv.w;
    }
#pragma unroll
    for (int s = 16; s; s >>= 1) {
        d1 += __shfl_xor_sync(0xffffffffu, d1, s);
        d2 += __shfl_xor_sync(0xffffffffu, d2, s);
    }
    if (lane == 0) {
        g_s1[gw] = d1;
        g_s2[gw] = d2;
        g_s2t[((size_t)b * N + n) * H + hh] = d2;
    }
}

// ---------------- Kernel 3: masked softmax stats, all 8 heads, per (b,i) --
__global__ void k_stats_multi(const float* __restrict__ adj) {
    const int bi = blockIdx.x;            // b*N + i
    const int b  = bi >> 11;
    const int i  = bi & (N - 1);
    const int tid = threadIdx.x, lane = tid & 31, wid = tid >> 5;

    float s1v[H];
#pragma unroll
    for (int hh = 0; hh < H; hh++) s1v[hh] = g_s1[(b * H + hh) * N + i];

    float mx[H], zs[H];
#pragma unroll
    for (int hh = 0; hh < H; hh++) { mx[hh] = -1e30f; zs[hh] = 0.f; }

    const float* arow = adj + (size_t)bi * N;
    for (int j = tid; j < N; j += 256) {
        if (arow[j] > 0.f) {
            const float4* s2p = (const float4*)(g_s2t + (size_t)(b * N + j) * H);
            const float4 sa = s2p[0], sb = s2p[1];
            const float sv[8] = {sa.x, sa.y, sa.z, sa.w, sb.x, sb.y, sb.z, sb.w};
#pragma unroll
            for (int hh = 0; hh < H; hh++) {
                float e = lrelu(s1v[hh] + sv[hh]);
                if (e > mx[hh]) { zs[hh] = zs[hh] * __expf(mx[hh] - e) + 1.f; mx[hh] = e; }
                else            { zs[hh] += __expf(e - mx[hh]); }
            }
        }
    }
    // warp combine
#pragma unroll
    for (int hh = 0; hh < H; hh++) {
        for (int s = 16; s; s >>= 1) {
            const float om = __shfl_xor_sync(0xffffffffu, mx[hh], s);
            const float oz = __shfl_xor_sync(0xffffffffu, zs[hh], s);
            const float nm = fmaxf(mx[hh], om);
            zs[hh] = zs[hh] * __expf(mx[hh] - nm) + oz * __expf(om - nm);
            mx[hh] = nm;
        }
    }
    __shared__ float smm[8][8], smz[8][8];
    if (lane == 0) {
#pragma unroll
        for (int hh = 0; hh < H; hh++) { smm[wid][hh] = mx[hh]; smz[wid][hh] = zs[hh]; }
    }
    __syncthreads();
    if (tid < 8) {
        float m = smm[0][tid], z = smz[0][tid];
#pragma unroll
        for (int w = 1; w < 8; w++) {
            const float om = smm[w][tid], oz = smz[w][tid];
            const float nm = fmaxf(m, om);
            z = z * __expf(m - nm) + oz * __expf(om - nm);
            m = nm;
        }
        const int r = (b * H + tid) * N + i;
        g_m[r]  = m;
        g_rz[r] = 1.f / z;
    }
}

// ---------------- Kernel 4: multihead att@h + elu -> x1 (concat layout) ---
__global__ void k_attn_multi(const float* __restrict__ adj) {
    extern __shared__ float sm[];
    float* hs  = sm;                 // [TJ][O]
    float* ps  = sm + TJ * O;        // [TI][65]
    float* s1s = ps + TI * 65;
    float* ms  = s1s + 64;
    float* rzs = ms + 64;
    float* s2s = rzs + 64;

    const int bh = blockIdx.y;
    const int b  = bh >> 3;
    const int i0 = blockIdx.x * TI;
    const int tid = threadIdx.x, tx = tid & 15, ty = tid >> 4;

    if (tid < 64) {
        const int r = bh * N + i0 + tid;
        s1s[tid] = g_s1[r];
        ms[tid]  = g_m[r];
        rzs[tid] = g_rz[r];
    }
    float acc[4][16] = {};
    const float* hb    = g_h + (size_t)bh * N * O;
    const float* arow0 = adj + ((size_t)b * N + i0) * N;

    for (int j0 = 0; j0 < N; j0 += TJ) {
        __syncthreads();   // previous gemm done (and initial stats visible)
#pragma unroll
        for (int t = 0; t < 16; t++) {
            const int idx = t * 256 + tid;
            const int jj = idx >> 6, o4 = idx & 63;
            *(float4*)&hs[jj * O + (o4 << 2)] =
                *(const float4*)&hb[(size_t)(j0 + jj) * O + (o4 << 2)];
        }
        if (tid < 64) s2s[tid] = g_s2[bh * N + j0 + tid];
        __syncthreads();
#pragma unroll
        for (int t = 0; t < 16; t++) {
            const int idx = t * 256 + tid;
            const int i = idx >> 6, jj = idx & 63;
            const float av = arow0[(size_t)i * N + j0 + jj];
            float p = 0.f;
            if (av > 0.f) {
                const float e = lrelu(s1s[i] + s2s[jj]);
                p = __expf(e - ms[i]) * rzs[i];
            }
            ps[i * 65 + jj] = p;
        }
        __syncthreads();
#pragma unroll 2
        for (int jj = 0; jj < TJ; jj++) {
            float hv[16];
#pragma unroll
            for (int q = 0; q < 4; q++) {
                const float4 t4 = *(const float4*)&hs[jj * O + q * 64 + (tx << 2)];
                hv[q * 4 + 0] = t4.x; hv[q * 4 + 1] = t4.y;
                hv[q * 4 + 2] = t4.z; hv[q * 4 + 3] = t4.w;
            }
#pragma unroll
            for (int r = 0; r < 4; r++) {
                const float p = ps[((ty << 2) + r) * 65 + jj];
#pragma unroll
                for (int c = 0; c < 16; c++) acc[r][c] += p * hv[c];
            }
        }
    }
#pragma unroll
    for (int r = 0; r < 4; r++) {
        const int i = i0 + (ty << 2) + r;
        float* dst = g_x1 + ((size_t)b * N + i) * HO + (bh & 7) * O;
#pragma unroll
        for (int q = 0; q < 4; q++) {
            float4 v = {eluf(acc[r][q * 4 + 0]), eluf(acc[r][q * 4 + 1]),
                        eluf(acc[r][q * 4 + 2]), eluf(acc[r][q * 4 + 3])};
            *(float4*)&dst[q * 64 + (tx << 2)] = v;
        }
    }
}

// ---------------- Kernel 5: fused h2 = x1@W_out, x2 = x1@W_lin^T + b -----
__global__ void k_gemm_dual(const float* __restrict__ Wout,
                            const float* __restrict__ Wlin,
                            const float* __restrict__ blin) {
    const int b  = blockIdx.z;
    const float* A = g_x1 + (size_t)b * N * HO;
    const int i0 = blockIdx.y * 64, n0 = blockIdx.x * 64;
    __shared__ float As [16][64];
    __shared__ float B1s[16][64];
    __shared__ float B2s[16][64];
    const int tid  = threadIdx.x;
    const int tx   = tid & 15, ty = tid >> 4;
    const int arow = tid >> 2, acol = (tid & 3) << 2;
    const int brow = tid >> 4, bcol = (tid & 15) << 2;
    const int c2   = tid >> 2, k2 = (tid & 3) << 2;

    float acc1[4][4] = {}, acc2[4][4] = {};
    for (int k0 = 0; k0 < HO; k0 += 16) {
        float4 av = *(const float4*)(A + (size_t)(i0 + arow) * HO + k0 + acol);
        As[acol + 0][arow] = av.x; As[acol + 1][arow] = av.y;
        As[acol + 2][arow] = av.z; As[acol + 3][arow] = av.w;
        *(float4*)&B1s[brow][bcol] =
            *(const float4*)(Wout + (size_t)(k0 + brow) * O + n0 + bcol);
        float4 wv = *(const float4*)(Wlin + (size_t)(n0 + c2) * HO + k0 + k2);
        B2s[k2 + 0][c2] = wv.x; B2s[k2 + 1][c2] = wv.y;
        B2s[k2 + 2][c2] = wv.z; B2s[k2 + 3][c2] = wv.w;
        __syncthreads();
#pragma unroll
        for (int kk = 0; kk < 16; kk++) {
            const float4 b1 = *(const float4*)&B1s[kk][tx << 2];
            const float4 b2 = *(const float4*)&B2s[kk][tx << 2];
            const float bb1[4] = {b1.x, b1.y, b1.z, b1.w};
            const float bb2[4] = {b2.x, b2.y, b2.z, b2.w};
#pragma unroll
            for (int r = 0; r < 4; r++) {
                const float a = As[kk][(ty << 2) + r];
#pragma unroll
                for (int c = 0; c < 4; c++) {
                    acc1[r][c] += a * bb1[c];
                    acc2[r][c] += a * bb2[c];
                }
            }
        }
        __syncthreads();
    }
    const float4 bias = *(const float4*)(blin + n0 + (tx << 2));
    const float bb[4] = {bias.x, bias.y, bias.z, bias.w};
#pragma unroll
    for (int r = 0; r < 4; r++) {
        const size_t row = (size_t)b * N + i0 + (ty << 2) + r;
        float4 v1 = {acc1[r][0], acc1[r][1], acc1[r][2], acc1[r][3]};
        float4 v2 = {acc2[r][0] + bb[0], acc2[r][1] + bb[1],
                     acc2[r][2] + bb[2], acc2[r][3] + bb[3]};
        *(float4*)(g_h2 + row * O + n0 + (tx << 2)) = v1;
        *(float4*)(g_x2 + row * O + n0 + (tx << 2)) = v2;
    }
}

// ---------------- Kernel 6: single-head s dots ----------------------------
__global__ void k_sdots_single(const float* __restrict__ aout) {
    const int gt = blockIdx.x * 256 + threadIdx.x;
    const int gw = gt >> 5, lane = gt & 31;   // gw in [0, B*N)
    const float4* hr = (const float4*)(g_h2 + (size_t)gw * O);
    const float4* a1 = (const float4*)(aout);
    const float4* a2 = (const float4*)(aout + O);
    float d1 = 0.f, d2 = 0.f;
#pragma unroll
    for (int t = 0; t < 2; t++) {
        const int idx = lane * 2 + t;
        const float4 hv = hr[idx], av = a1[idx], bv = a2[idx];
        d1 += hv.x * av.x + hv.y * av.y + hv.z * av.z + hv.w * av.w;
        d2 += hv.x * bv.x + hv.y * bv.y + hv.z * bv.z + hv.w * bv.w;
    }
#pragma unroll
    for (int s = 16; s; s >>= 1) {
        d1 += __shfl_xor_sync(0xffffffffu, d1, s);
        d2 += __shfl_xor_sync(0xffffffffu, d2, s);
    }
    if (lane == 0) { g_s1b[gw] = d1; g_s2b[gw] = d2; }
}

// ---------------- Kernel 7: single-head softmax stats ---------------------
__global__ void k_stats_single(const float* __restrict__ adj) {
    const int bi = blockIdx.x;
    const int b  = bi >> 11;
    const int tid = threadIdx.x, lane = tid & 31, wid = tid >> 5;
    const float s1v = g_s1b[bi];
    const float* arow = adj + (size_t)bi * N;
    float mx = -1e30f, zs = 0.f;
    for (int j = tid; j < N; j += 256) {
        if (arow[j] > 0.f) {
            float e = lrelu(s1v + g_s2b[b * N + j]);
            if (e > mx) { zs = zs * __expf(mx - e) + 1.f; mx = e; }
            else        { zs += __expf(e - mx); }
        }
    }
    for (int s = 16; s; s >>= 1) {
        const float om = __shfl_xor_sync(0xffffffffu, mx, s);
        const float oz = __shfl_xor_sync(0xffffffffu, zs, s);
        const float nm = fmaxf(mx, om);
        zs = zs * __expf(mx - nm) + oz * __expf(om - nm);
        mx = nm;
    }
    __shared__ float smm[8], smz[8];
    if (lane == 0) { smm[wid] = mx; smz[wid] = zs; }
    __syncthreads();
    if (tid == 0) {
        float m = smm[0], z = smz[0];
#pragma unroll
        for (int w = 1; w < 8; w++) {
            const float nm = fmaxf(m, smm[w]);
            z = z * __expf(m - nm) + smz[w] * __expf(smm[w] - nm);
            m = nm;
        }
        g_mb[bi]  = m;
        g_rzb[bi] = 1.f / z;
    }
}

// ---------------- Kernel 8: single-head att2@h2, split-j, += into x2 ------
__global__ void k_attn_single(const float* __restrict__ adj) {
    extern __shared__ float sm[];
    float* hs  = sm;
    float* ps  = sm + TJ * O;
    float* s1s = ps + TI * 65;
    float* ms  = s1s + 64;
    float* rzs = ms + 64;
    float* s2s = rzs + 64;

    const int b  = blockIdx.y;
    const int i0 = blockIdx.x * TI;
    const int js = blockIdx.z;            // j-partition 0..7 (256 cols each)
    const int tid = threadIdx.x, tx = tid & 15, ty = tid >> 4;

    if (tid < 64) {
        const int r = b * N + i0 + tid;
        s1s[tid] = g_s1b[r];
        ms[tid]  = g_mb[r];
        rzs[tid] = g_rzb[r];
    }
    float acc[4][16] = {};
    const float* hb    = g_h2 + (size_t)b * N * O;
    const float* arow0 = adj + ((size_t)b * N + i0) * N;

    const int jbeg = js * (N / 8), jend = jbeg + (N / 8);
    for (int j0 = jbeg; j0 < jend; j0 += TJ) {
        __syncthreads();
#pragma unroll
        for (int t = 0; t < 16; t++) {
            const int idx = t * 256 + tid;
            const int jj = idx >> 6, o4 = idx & 63;
            *(float4*)&hs[jj * O + (o4 << 2)] =
                *(const float4*)&hb[(size_t)(j0 + jj) * O + (o4 << 2)];
        }
        if (tid < 64) s2s[tid] = g_s2b[b * N + j0 + tid];
        __syncthreads();
#pragma unroll
        for (int t = 0; t < 16; t++) {
            const int idx = t * 256 + tid;
            const int i = idx >> 6, jj = idx & 63;
            const float av = arow0[(size_t)i * N + j0 + jj];
            float p = 0.f;
            if (av > 0.f) {
                const float e = lrelu(s1s[i] + s2s[jj]);
                p = __expf(e - ms[i]) * rzs[i];
            }
            ps[i * 65 + jj] = p;
        }
        __syncthreads();
#pragma unroll 2
        for (int jj = 0; jj < TJ; jj++) {
            float hv[16];
#pragma unroll
            for (int q = 0; q < 4; q++) {
                const float4 t4 = *(const float4*)&hs[jj * O + q * 64 + (tx << 2)];
                hv[q * 4 + 0] = t4.x; hv[q * 4 + 1] = t4.y;
                hv[q * 4 + 2] = t4.z; hv[q * 4 + 3] = t4.w;
            }
#pragma unroll
            for (int r = 0; r < 4; r++) {
                const float p = ps[((ty << 2) + r) * 65 + jj];
#pragma unroll
                for (int c = 0; c < 16; c++) acc[r][c] += p * hv[c];
            }
        }
    }
#pragma unroll
    for (int r = 0; r < 4; r++) {
        const int i = i0 + (ty << 2) + r;
        float* dst = g_x2 + ((size_t)b * N + i) * O;
#pragma unroll
        for (int q = 0; q < 4; q++) {
#pragma unroll
            for (int c = 0; c < 4; c++)
                atomicAdd(&dst[q * 64 + (tx << 2) + c], acc[r][q * 4 + c]);
        }
    }
}

// ---------------- Kernel 9: out = relu(x2 @ W_ln^T + b_ln) ----------------
__global__ void k_gemm_out(const float* __restrict__ Wln,
                           const float* __restrict__ bln,
                           float* __restrict__ out) {
    const float* A = g_x2;                 // [B*N][O]
    const int i0 = blockIdx.y * 64, n0 = blockIdx.x * 64;
    __shared__ float As[16][64];
    __shared__ float Bs[16][64];
    const int tid  = threadIdx.x;
    const int tx   = tid & 15, ty = tid >> 4;
    const int arow = tid >> 2, acol = (tid & 3) << 2;
    const int c2   = tid >> 2, k2 = (tid & 3) << 2;

    float acc[4][4] = {};
    for (int k0 = 0; k0 < O; k0 += 16) {
        float4 av = *(const float4*)(A + (size_t)(i0 + arow) * O + k0 + acol);
        As[acol + 0][arow] = av.x; As[acol + 1][arow] = av.y;
        As[acol + 2][arow] = av.z; As[acol + 3][arow] = av.w;
        float4 wv = *(const float4*)(Wln + (size_t)(n0 + c2) * O + k0 + k2);
        Bs[k2 + 0][c2] = wv.x; Bs[k2 + 1][c2] = wv.y;
        Bs[k2 + 2][c2] = wv.z; Bs[k2 + 3][c2] = wv.w;
        __syncthreads();
#pragma unroll
        for (int kk = 0; kk < 16; kk++) {
            const float4 bv = *(const float4*)&Bs[kk][tx << 2];
            const float bb[4] = {bv.x, bv.y, bv.z, bv.w};
#pragma unroll
            for (int r = 0; r < 4; r++) {
                const float a = As[kk][(ty << 2) + r];
#pragma unroll
                for (int c = 0; c < 4; c++) acc[r][c] += a * bb[c];
            }
        }
        __syncthreads();
    }
    const float4 bias = *(const float4*)(bln + n0 + (tx << 2));
    const float bb[4] = {bias.x, bias.y, bias.z, bias.w};
#pragma unroll
    for (int r = 0; r < 4; r++) {
        float4 v = {fmaxf(acc[r][0] + bb[0], 0.f), fmaxf(acc[r][1] + bb[1], 0.f),
                    fmaxf(acc[r][2] + bb[2], 0.f), fmaxf(acc[r][3] + bb[3], 0.f)};
        *(float4*)(out + (size_t)(i0 + (ty << 2) + r) * O + n0 + (tx << 2)) = v;
    }
}

// ---------------- launch --------------------------------------------------
extern "C" void kernel_launch(void* const* d_in, const int* in_sizes, int n_in,
                              void* d_out, int out_size) {
    const float* x       = (const float*)d_in[0];
    const float* adj     = (const float*)d_in[1];
    // d_in[2] = mask (unused by the reference forward)
    const float* W_heads = (const float*)d_in[3];
    const float* a_heads = (const float*)d_in[4];
    const float* W_out   = (const float*)d_in[5];
    const float* a_out   = (const float*)d_in[6];
    const float* W_lin   = (const float*)d_in[7];
    const float* b_lin   = (const float*)d_in[8];
    const float* W_ln    = (const float*)d_in[9];
    const float* b_ln    = (const float*)d_in[10];
    float* out = (float*)d_out;

    cudaFuncSetAttribute(k_attn_multi,  cudaFuncAttributeMaxDynamicSharedMemorySize, SMEM_ATTN);
    cudaFuncSetAttribute(k_attn_single, cudaFuncAttributeMaxDynamicSharedMemorySize, SMEM_ATTN);

    k_gemm_h     <<<dim3(O / 64, N / 64, B * H), 256>>>(x, W_heads);
    k_sdots_multi<<<(B * H * N) / 8, 256>>>(a_heads);
    k_stats_multi<<<B * N, 256>>>(adj);
    k_attn_multi <<<dim3(N / 64, B * H), 256, SMEM_ATTN>>>(adj);
    k_gemm_dual  <<<dim3(O / 64, N / 64, B), 256>>>(W_out, W_lin, b_lin);
    k_sdots_single<<<(B * N) / 8, 256>>>(a_out);
    k_stats_single<<<B * N, 256>>>(adj);
    k_attn_single<<<dim3(N / 64, B, 8), 256, SMEM_ATTN>>>(adj);
    k_gemm_out   <<<dim3(O / 64, (B * N) / 64), 256>>>(W_ln, b_ln, out);
}

// round 5
// speedup vs baseline: 1.4200x; 1.4200x over previous
#include <cuda_runtime.h>
#include <cstdint>

// Problem constants
namespace {
constexpr int B = 2, N = 2048, F = 768, H = 8, O = 256, HO = H * O;
constexpr float ALPHA = 0.2f;
constexpr int KC = 32;                 // j-chunk for mma attention
constexpr int NCHUNK = N / KC;         // 64
// mma-attn smem layout (float offsets)
constexpr int PSF    = 128 * 36;       // one p buffer (padded stride 36)
constexpr int HSF    = 32 * 264;       // one h buffer (padded stride 264)
constexpr int OFF_PS = 0;
constexpr int OFF_HS = 2 * PSF;        // 9216
constexpr int OFF_S1 = OFF_HS + 2 * HSF;   // 26112
constexpr int OFF_M  = OFF_S1 + 128;
constexpr int OFF_RZ = OFF_M + 128;
constexpr int SMEM_MMA_BYTES = (OFF_RZ + 128) * 4;  // 105984
}

// ---------------- scratch (static device globals; no allocation) ----------
__device__ float g_h  [(size_t)B * H * N * O];   // layer0 per-head features
__device__ float g_s1 [B * H * N];
__device__ float g_s2 [B * H * N];
__device__ float g_s2t[B * N * H];
__device__ float g_m  [B * H * N];
__device__ float g_rz [B * H * N];
__device__ float g_x1 [(size_t)B * N * HO];
__device__ float g_h2 [(size_t)B * N * O];
__device__ float g_x2 [(size_t)B * N * O];
__device__ float g_s1b[B * N];
__device__ float g_s2b[B * N];
__device__ float g_mb [B * N];
__device__ float g_rzb[B * N];

__device__ __forceinline__ float lrelu(float v) { return v > 0.f ? v : ALPHA * v; }
__device__ __forceinline__ float eluf(float v)  { return v > 0.f ? v : __expf(v) - 1.f; }

// m16n8k8 tf32 mma (portable PTX, works on bare sm_103 target)
__device__ __forceinline__ void mma_tf32(float* c, const uint32_t* a,
                                         uint32_t b0, uint32_t b1) {
    asm volatile(
        "mma.sync.aligned.m16n8k8.row.col.f32.tf32.tf32.f32 "
        "{%0,%1,%2,%3}, {%4,%5,%6,%7}, {%8,%9}, {%0,%1,%2,%3};"
        : "+f"(c[0]), "+f"(c[1]), "+f"(c[2]), "+f"(c[3])
        : "r"(a[0]), "r"(a[1]), "r"(a[2]), "r"(a[3]), "r"(b0), "r"(b1));
}

// ---------------- Kernel 1: h[b,h] = x[b] @ W_heads[h] --------------------
__global__ void k_gemm_h(const float* __restrict__ x, const float* __restrict__ Wh) {
    const int bh = blockIdx.z;
    const int b  = bh >> 3;
    const float* A  = x  + (size_t)b * N * F;
    const float* Bw = Wh + (size_t)(bh & 7) * F * O;
    float* C = g_h + (size_t)bh * N * O;
    const int i0 = blockIdx.y * 64;
    const int n0 = blockIdx.x * 64;
    __shared__ float As[16][64];
    __shared__ float Bs[16][64];
    const int tid  = threadIdx.x;
    const int tx   = tid & 15, ty = tid >> 4;
    const int arow = tid >> 2, acol = (tid & 3) << 2;
    const int brow = tid >> 4, bcol = (tid & 15) << 2;

    float acc[4][4] = {};
    for (int k0 = 0; k0 < F; k0 += 16) {
        float4 av = *(const float4*)(A + (size_t)(i0 + arow) * F + k0 + acol);
        As[acol + 0][arow] = av.x; As[acol + 1][arow] = av.y;
        As[acol + 2][arow] = av.z; As[acol + 3][arow] = av.w;
        *(float4*)&Bs[brow][bcol] =
            *(const float4*)(Bw + (size_t)(k0 + brow) * O + n0 + bcol);
        __syncthreads();
#pragma unroll
        for (int kk = 0; kk < 16; kk++) {
            const float4 bv = *(const float4*)&Bs[kk][tx << 2];
            const float bb[4] = {bv.x, bv.y, bv.z, bv.w};
#pragma unroll
            for (int r = 0; r < 4; r++) {
                const float a = As[kk][(ty << 2) + r];
#pragma unroll
                for (int c = 0; c < 4; c++) acc[r][c] += a * bb[c];
            }
        }
        __syncthreads();
    }
#pragma unroll
    for (int r = 0; r < 4; r++) {
        float4 v = {acc[r][0], acc[r][1], acc[r][2], acc[r][3]};
        *(float4*)(C + (size_t)(i0 + (ty << 2) + r) * O + n0 + (tx << 2)) = v;
    }
}

// ---------------- Kernel 2: s1/s2 dots (multi-head) -----------------------
__global__ void k_sdots_multi(const float* __restrict__ ah) {
    const int gt = blockIdx.x * 256 + threadIdx.x;
    const int gw = gt >> 5, lane = gt & 31;
    const int hh = (gw / N) & 7;
    const int b  = gw / (N * H);
    const int n  = gw % N;
    const float4* hr = (const float4*)(g_h + (size_t)gw * O);
    const float4* a1 = (const float4*)(ah + (size_t)hh * 2 * O);
    const float4* a2 = a1 + O / 4;
    float d1 = 0.f, d2 = 0.f;
#pragma unroll
    for (int t = 0; t < 2; t++) {
        const int idx = lane * 2 + t;
        const float4 hv = hr[idx], av = a1[idx], bv = a2[idx];
        d1 += hv.x * av.x + hv.y * av.y + hv.z * av.z + hv.w * av.w;
        d2 += hv.x * bv.x + hv.y * bv.y + hv.z * bv.z + hv.w * bv.w;
    }
#pragma unroll
    for (int s = 16; s; s >>= 1) {
        d1 += __shfl_xor_sync(0xffffffffu, d1, s);
        d2 += __shfl_xor_sync(0xffffffffu, d2, s);
    }
    if (lane == 0) {
        g_s1[gw] = d1;
        g_s2[gw] = d2;
        g_s2t[((size_t)b * N + n) * H + hh] = d2;
    }
}

// ---------------- Kernel 3: masked softmax stats (8 heads) ----------------
__global__ void k_stats_multi(const float* __restrict__ adj) {
    const int bi = blockIdx.x;
    const int b  = bi >> 11;
    const int i  = bi & (N - 1);
    const int tid = threadIdx.x, lane = tid & 31, wid = tid >> 5;

    float s1v[H];
#pragma unroll
    for (int hh = 0; hh < H; hh++) s1v[hh] = g_s1[(b * H + hh) * N + i];
    float mx[H], zs[H];
#pragma unroll
    for (int hh = 0; hh < H; hh++) { mx[hh] = -1e30f; zs[hh] = 0.f; }

    const float* arow = adj + (size_t)bi * N;
    for (int j = tid; j < N; j += 256) {
        if (arow[j] > 0.f) {
            const float4* s2p = (const float4*)(g_s2t + (size_t)(b * N + j) * H);
            const float4 sa = s2p[0], sb = s2p[1];
            const float sv[8] = {sa.x, sa.y, sa.z, sa.w, sb.x, sb.y, sb.z, sb.w};
#pragma unroll
            for (int hh = 0; hh < H; hh++) {
                float e = lrelu(s1v[hh] + sv[hh]);
                if (e > mx[hh]) { zs[hh] = zs[hh] * __expf(mx[hh] - e) + 1.f; mx[hh] = e; }
                else            { zs[hh] += __expf(e - mx[hh]); }
            }
        }
    }
#pragma unroll
    for (int hh = 0; hh < H; hh++) {
        for (int s = 16; s; s >>= 1) {
            const float om = __shfl_xor_sync(0xffffffffu, mx[hh], s);
            const float oz = __shfl_xor_sync(0xffffffffu, zs[hh], s);
            const float nm = fmaxf(mx[hh], om);
            zs[hh] = zs[hh] * __expf(mx[hh] - nm) + oz * __expf(om - nm);
            mx[hh] = nm;
        }
    }
    __shared__ float smm[8][8], smz[8][8];
    if (lane == 0) {
#pragma unroll
        for (int hh = 0; hh < H; hh++) { smm[wid][hh] = mx[hh]; smz[wid][hh] = zs[hh]; }
    }
    __syncthreads();
    if (tid < 8) {
        float m = smm[0][tid], z = smz[0][tid];
#pragma unroll
        for (int w = 1; w < 8; w++) {
            const float om = smm[w][tid], oz = smz[w][tid];
            const float nm = fmaxf(m, om);
            z = z * __expf(m - nm) + oz * __expf(om - nm);
            m = nm;
        }
        const int r = (b * H + tid) * N + i;
        g_m[r]  = m;
        g_rz[r] = 1.f / z;
    }
}

// ---------------- mma.sync tf32 attention GEMM ----------------------------
// MODE 0: multihead, D = p@h -> elu -> x1 concat. MODE 1: single, x2 += p@h2.
template <int MODE>
__global__ void __launch_bounds__(512, 1) k_attn_mma(const float* __restrict__ adj) {
    extern __shared__ float sm[];
    float* s1s = sm + OFF_S1;
    float* ms  = sm + OFF_M;
    float* rzs = sm + OFF_RZ;

    const int tid = threadIdx.x;
    const int lane = tid & 31, wid = tid >> 5;
    const int wm = wid >> 2, wn = wid & 3;          // 4x4 warp grid
    const int quad = lane >> 2, four = lane & 3;
    const int bh = blockIdx.y;
    const int b  = MODE ? bh : (bh >> 3);
    const int i0 = blockIdx.x * 128;

    const float* s1g  = MODE ? g_s1b : g_s1;
    const float* s2g  = MODE ? g_s2b : g_s2;
    const float* mg   = MODE ? g_mb  : g_m;
    const float* rzg  = MODE ? g_rzb : g_rz;
    const float* hsrc = (MODE ? g_h2 : g_h) + (size_t)bh * N * O;

    if (tid < 128) {
        const int r = bh * N + i0 + tid;
        s1s[tid] = s1g[r]; ms[tid] = mg[r]; rzs[tid] = rzg[r];
    }
    __syncthreads();

    // staging roles
    const int pi = tid >> 2, pj = (tid & 3) << 3;        // p: row, 8 cols
    const int hr = tid >> 4, hc = (tid & 15) << 4;       // h: row, 16 cols
    const float* adjrow = adj + ((size_t)(b * N + i0 + pi)) * N;
    const float  s1v = s1s[pi], mm = ms[pi], rz = rzs[pi];

    float4 av0, av1, sv0, sv1, hv0, hv1, hv2, hv3;
    // load chunk 0
    {
        av0 = *(const float4*)(adjrow + pj);
        av1 = *(const float4*)(adjrow + pj + 4);
        sv0 = *(const float4*)(s2g + bh * N + pj);
        sv1 = *(const float4*)(s2g + bh * N + pj + 4);
        const float* hrow = hsrc + (size_t)hr * O + hc;
        hv0 = *(const float4*)(hrow);
        hv1 = *(const float4*)(hrow + 4);
        hv2 = *(const float4*)(hrow + 8);
        hv3 = *(const float4*)(hrow + 12);
    }
    // store chunk 0 -> buf 0
    {
        float* P = sm + OFF_PS;
        float4 p0, p1;
        p0.x = (av0.x > 0.f) ? __expf(lrelu(s1v + sv0.x) - mm) * rz : 0.f;
        p0.y = (av0.y > 0.f) ? __expf(lrelu(s1v + sv0.y) - mm) * rz : 0.f;
        p0.z = (av0.z > 0.f) ? __expf(lrelu(s1v + sv0.z) - mm) * rz : 0.f;
        p0.w = (av0.w > 0.f) ? __expf(lrelu(s1v + sv0.w) - mm) * rz : 0.f;
        p1.x = (av1.x > 0.f) ? __expf(lrelu(s1v + sv1.x) - mm) * rz : 0.f;
        p1.y = (av1.y > 0.f) ? __expf(lrelu(s1v + sv1.y) - mm) * rz : 0.f;
        p1.z = (av1.z > 0.f) ? __expf(lrelu(s1v + sv1.z) - mm) * rz : 0.f;
        p1.w = (av1.w > 0.f) ? __expf(lrelu(s1v + sv1.w) - mm) * rz : 0.f;
        *(float4*)(P + pi * 36 + pj)     = p0;
        *(float4*)(P + pi * 36 + pj + 4) = p1;
        float* Hd = sm + OFF_HS + hr * 264 + hc;
        *(float4*)(Hd)      = hv0;
        *(float4*)(Hd + 4)  = hv1;
        *(float4*)(Hd + 8)  = hv2;
        *(float4*)(Hd + 12) = hv3;
    }
    __syncthreads();

    float acc[2][8][4] = {};

    for (int k = 0; k < NCHUNK; k++) {
        const int s = k & 1;
        const int j1 = (k + 1) * KC;
        if (k + 1 < NCHUNK) {
            av0 = *(const float4*)(adjrow + j1 + pj);
            av1 = *(const float4*)(adjrow + j1 + pj + 4);
            sv0 = *(const float4*)(s2g + bh * N + j1 + pj);
            sv1 = *(const float4*)(s2g + bh * N + j1 + pj + 4);
            const float* hrow = hsrc + (size_t)(j1 + hr) * O + hc;
            hv0 = *(const float4*)(hrow);
            hv1 = *(const float4*)(hrow + 4);
            hv2 = *(const float4*)(hrow + 8);
            hv3 = *(const float4*)(hrow + 12);
        }
        // mma on buffer s
        {
            const float* P  = sm + OFF_PS + s * PSF;
            const float* Hs = sm + OFF_HS + s * HSF;
#pragma unroll
            for (int kq = 0; kq < 4; kq++) {
                const int colA = (kq << 3) + four;
                uint32_t a[2][4];
#pragma unroll
                for (int smi = 0; smi < 2; smi++) {
                    const int rA = wm * 32 + smi * 16 + quad;
                    a[smi][0] = __float_as_uint(P[rA * 36 + colA]);
                    a[smi][1] = __float_as_uint(P[(rA + 8) * 36 + colA]);
                    a[smi][2] = __float_as_uint(P[rA * 36 + colA + 4]);
                    a[smi][3] = __float_as_uint(P[(rA + 8) * 36 + colA + 4]);
                }
                const int rB0 = ((kq << 3) + four) * 264;
                const int rB1 = rB0 + 4 * 264;
#pragma unroll
                for (int sn = 0; sn < 8; sn++) {
                    const int nb = wn * 64 + sn * 8 + quad;
                    const uint32_t b0 = __float_as_uint(Hs[rB0 + nb]);
                    const uint32_t b1 = __float_as_uint(Hs[rB1 + nb]);
                    mma_tf32(acc[0][sn], a[0], b0, b1);
                    mma_tf32(acc[1][sn], a[1], b0, b1);
                }
            }
        }
        // store chunk k+1 -> buffer s^1
        if (k + 1 < NCHUNK) {
            float* P = sm + OFF_PS + (s ^ 1) * PSF;
            float4 p0, p1;
            p0.x = (av0.x > 0.f) ? __expf(lrelu(s1v + sv0.x) - mm) * rz : 0.f;
            p0.y = (av0.y > 0.f) ? __expf(lrelu(s1v + sv0.y) - mm) * rz : 0.f;
            p0.z = (av0.z > 0.f) ? __expf(lrelu(s1v + sv0.z) - mm) * rz : 0.f;
            p0.w = (av0.w > 0.f) ? __expf(lrelu(s1v + sv0.w) - mm) * rz : 0.f;
            p1.x = (av1.x > 0.f) ? __expf(lrelu(s1v + sv1.x) - mm) * rz : 0.f;
            p1.y = (av1.y > 0.f) ? __expf(lrelu(s1v + sv1.y) - mm) * rz : 0.f;
            p1.z = (av1.z > 0.f) ? __expf(lrelu(s1v + sv1.z) - mm) * rz : 0.f;
            p1.w = (av1.w > 0.f) ? __expf(lrelu(s1v + sv1.w) - mm) * rz : 0.f;
            *(float4*)(P + pi * 36 + pj)     = p0;
            *(float4*)(P + pi * 36 + pj + 4) = p1;
            float* Hd = sm + OFF_HS + (s ^ 1) * HSF + hr * 264 + hc;
            *(float4*)(Hd)      = hv0;
            *(float4*)(Hd + 4)  = hv1;
            *(float4*)(Hd + 8)  = hv2;
            *(float4*)(Hd + 12) = hv3;
        }
        __syncthreads();
    }

    // epilogue: C[row][col] per m16n8 fragment layout
#pragma unroll
    for (int smi = 0; smi < 2; smi++) {
#pragma unroll
        for (int sn = 0; sn < 8; sn++) {
            const int row0 = i0 + wm * 32 + smi * 16 + quad;
            const int col  = wn * 64 + sn * 8 + (four << 1);
            const float* c = acc[smi][sn];
            if (MODE == 0) {
                float* d0 = g_x1 + ((size_t)b * N + row0) * HO + (bh & 7) * O + col;
                float* d1 = d0 + (size_t)8 * HO;
                float2 v0 = {eluf(c[0]), eluf(c[1])};
                float2 v1 = {eluf(c[2]), eluf(c[3])};
                *(float2*)d0 = v0;
                *(float2*)d1 = v1;
            } else {
                float* d0 = g_x2 + ((size_t)b * N + row0) * O + col;
                float* d1 = d0 + (size_t)8 * O;
                float2 o0 = *(float2*)d0, o1 = *(float2*)d1;
                o0.x += c[0]; o0.y += c[1];
                o1.x += c[2]; o1.y += c[3];
                *(float2*)d0 = o0;
                *(float2*)d1 = o1;
            }
        }
    }
}

// ---------------- Kernel 5: fused h2 = x1@W_out, x2 = x1@W_lin^T + b ------
__global__ void k_gemm_dual(const float* __restrict__ Wout,
                            const float* __restrict__ Wlin,
                            const float* __restrict__ blin) {
    const int b  = blockIdx.z;
    const float* A = g_x1 + (size_t)b * N * HO;
    const int i0 = blockIdx.y * 64, n0 = blockIdx.x * 64;
    __shared__ float As [16][64];
    __shared__ float B1s[16][64];
    __shared__ float B2s[16][64];
    const int tid  = threadIdx.x;
    const int tx   = tid & 15, ty = tid >> 4;
    const int arow = tid >> 2, acol = (tid & 3) << 2;
    const int brow = tid >> 4, bcol = (tid & 15) << 2;
    const int c2   = tid >> 2, k2 = (tid & 3) << 2;

    float acc1[4][4] = {}, acc2[4][4] = {};
    for (int k0 = 0; k0 < HO; k0 += 16) {
        float4 av = *(const float4*)(A + (size_t)(i0 + arow) * HO + k0 + acol);
        As[acol + 0][arow] = av.x; As[acol + 1][arow] = av.y;
        As[acol + 2][arow] = av.z; As[acol + 3][arow] = av.w;
        *(float4*)&B1s[brow][bcol] =
            *(const float4*)(Wout + (size_t)(k0 + brow) * O + n0 + bcol);
        float4 wv = *(const float4*)(Wlin + (size_t)(n0 + c2) * HO + k0 + k2);
        B2s[k2 + 0][c2] = wv.x; B2s[k2 + 1][c2] = wv.y;
        B2s[k2 + 2][c2] = wv.z; B2s[k2 + 3][c2] = wv.w;
        __syncthreads();
#pragma unroll
        for (int kk = 0; kk < 16; kk++) {
            const float4 b1 = *(const float4*)&B1s[kk][tx << 2];
            const float4 b2 = *(const float4*)&B2s[kk][tx << 2];
            const float bb1[4] = {b1.x, b1.y, b1.z, b1.w};
            const float bb2[4] = {b2.x, b2.y, b2.z, b2.w};
#pragma unroll
            for (int r = 0; r < 4; r++) {
                const float a = As[kk][(ty << 2) + r];
#pragma unroll
                for (int c = 0; c < 4; c++) {
                    acc1[r][c] += a * bb1[c];
                    acc2[r][c] += a * bb2[c];
                }
            }
        }
        __syncthreads();
    }
    const float4 bias = *(const float4*)(blin + n0 + (tx << 2));
    const float bb[4] = {bias.x, bias.y, bias.z, bias.w};
#pragma unroll
    for (int r = 0; r < 4; r++) {
        const size_t row = (size_t)b * N + i0 + (ty << 2) + r;
        float4 v1 = {acc1[r][0], acc1[r][1], acc1[r][2], acc1[r][3]};
        float4 v2 = {acc2[r][0] + bb[0], acc2[r][1] + bb[1],
                     acc2[r][2] + bb[2], acc2[r][3] + bb[3]};
        *(float4*)(g_h2 + row * O + n0 + (tx << 2)) = v1;
        *(float4*)(g_x2 + row * O + n0 + (tx << 2)) = v2;
    }
}

// ---------------- Kernel 6: single-head s dots ----------------------------
__global__ void k_sdots_single(const float* __restrict__ aout) {
    const int gt = blockIdx.x * 256 + threadIdx.x;
    const int gw = gt >> 5, lane = gt & 31;
    const float4* hr = (const float4*)(g_h2 + (size_t)gw * O);
    const float4* a1 = (const float4*)(aout);
    const float4* a2 = (const float4*)(aout + O);
    float d1 = 0.f, d2 = 0.f;
#pragma unroll
    for (int t = 0; t < 2; t++) {
        const int idx = lane * 2 + t;
        const float4 hv = hr[idx], av = a1[idx], bv = a2[idx];
        d1 += hv.x * av.x + hv.y * av.y + hv.z * av.z + hv.w * av.w;
        d2 += hv.x * bv.x + hv.y * bv.y + hv.z * bv.z + hv.w * bv.w;
    }
#pragma unroll
    for (int s = 16; s; s >>= 1) {
        d1 += __shfl_xor_sync(0xffffffffu, d1, s);
        d2 += __shfl_xor_sync(0xffffffffu, d2, s);
    }
    if (lane == 0) { g_s1b[gw] = d1; g_s2b[gw] = d2; }
}

// ---------------- Kernel 7: single-head softmax stats ---------------------
__global__ void k_stats_single(const float* __restrict__ adj) {
    const int bi = blockIdx.x;
    const int b  = bi >> 11;
    const int tid = threadIdx.x, lane = tid & 31, wid = tid >> 5;
    const float s1v = g_s1b[bi];
    const float* arow = adj + (size_t)bi * N;
    float mx = -1e30f, zs = 0.f;
    for (int j = tid; j < N; j += 256) {
        if (arow[j] > 0.f) {
            float e = lrelu(s1v + g_s2b[b * N + j]);
            if (e > mx) { zs = zs * __expf(mx - e) + 1.f; mx = e; }
            else        { zs += __expf(e - mx); }
        }
    }
    for (int s = 16; s; s >>= 1) {
        const float om = __shfl_xor_sync(0xffffffffu, mx, s);
        const float oz = __shfl_xor_sync(0xffffffffu, zs, s);
        const float nm = fmaxf(mx, om);
        zs = zs * __expf(mx - nm) + oz * __expf(om - nm);
        mx = nm;
    }
    __shared__ float smm[8], smz[8];
    if (lane == 0) { smm[wid] = mx; smz[wid] = zs; }
    __syncthreads();
    if (tid == 0) {
        float m = smm[0], z = smz[0];
#pragma unroll
        for (int w = 1; w < 8; w++) {
            const float nm = fmaxf(m, smm[w]);
            z = z * __expf(m - nm) + smz[w] * __expf(smm[w] - nm);
            m = nm;
        }
        g_mb[bi]  = m;
        g_rzb[bi] = 1.f / z;
    }
}

// ---------------- Kernel 9: out = relu(x2 @ W_ln^T + b_ln) ----------------
__global__ void k_gemm_out(const float* __restrict__ Wln,
                           const float* __restrict__ bln,
                           float* __restrict__ out) {
    const float* A = g_x2;
    const int i0 = blockIdx.y * 64, n0 = blockIdx.x * 64;
    __shared__ float As[16][64];
    __shared__ float Bs[16][64];
    const int tid  = threadIdx.x;
    const int tx   = tid & 15, ty = tid >> 4;
    const int arow = tid >> 2, acol = (tid & 3) << 2;
    const int c2   = tid >> 2, k2 = (tid & 3) << 2;

    float acc[4][4] = {};
    for (int k0 = 0; k0 < O; k0 += 16) {
        float4 av = *(const float4*)(A + (size_t)(i0 + arow) * O + k0 + acol);
        As[acol + 0][arow] = av.x; As[acol + 1][arow] = av.y;
        As[acol + 2][arow] = av.z; As[acol + 3][arow] = av.w;
        float4 wv = *(const float4*)(Wln + (size_t)(n0 + c2) * O + k0 + k2);
        Bs[k2 + 0][c2] = wv.x; Bs[k2 + 1][c2] = wv.y;
        Bs[k2 + 2][c2] = wv.z; Bs[k2 + 3][c2] = wv.w;
        __syncthreads();
#pragma unroll
        for (int kk = 0; kk < 16; kk++) {
            const float4 bv = *(const float4*)&Bs[kk][tx << 2];
            const float bb[4] = {bv.x, bv.y, bv.z, bv.w};
#pragma unroll
            for (int r = 0; r < 4; r++) {
                const float a = As[kk][(ty << 2) + r];
#pragma unroll
                for (int c = 0; c < 4; c++) acc[r][c] += a * bb[c];
            }
        }
        __syncthreads();
    }
    const float4 bias = *(const float4*)(bln + n0 + (tx << 2));
    const float bb[4] = {bias.x, bias.y, bias.z, bias.w};
#pragma unroll
    for (int r = 0; r < 4; r++) {
        float4 v = {fmaxf(acc[r][0] + bb[0], 0.f), fmaxf(acc[r][1] + bb[1], 0.f),
                    fmaxf(acc[r][2] + bb[2], 0.f), fmaxf(acc[r][3] + bb[3], 0.f)};
        *(float4*)(out + (size_t)(i0 + (ty << 2) + r) * O + n0 + (tx << 2)) = v;
    }
}

// ---------------- launch --------------------------------------------------
extern "C" void kernel_launch(void* const* d_in, const int* in_sizes, int n_in,
                              void* d_out, int out_size) {
    const float* x       = (const float*)d_in[0];
    const float* adj     = (const float*)d_in[1];
    const float* W_heads = (const float*)d_in[3];
    const float* a_heads = (const float*)d_in[4];
    const float* W_out   = (const float*)d_in[5];
    const float* a_out   = (const float*)d_in[6];
    const float* W_lin   = (const float*)d_in[7];
    const float* b_lin   = (const float*)d_in[8];
    const float* W_ln    = (const float*)d_in[9];
    const float* b_ln    = (const float*)d_in[10];
    float* out = (float*)d_out;

    cudaFuncSetAttribute(k_attn_mma<0>, cudaFuncAttributeMaxDynamicSharedMemorySize, SMEM_MMA_BYTES);
    cudaFuncSetAttribute(k_attn_mma<1>, cudaFuncAttributeMaxDynamicSharedMemorySize, SMEM_MMA_BYTES);

    k_gemm_h      <<<dim3(O / 64, N / 64, B * H), 256>>>(x, W_heads);
    k_sdots_multi <<<(B * H * N) / 8, 256>>>(a_heads);
    k_stats_multi <<<B * N, 256>>>(adj);
    k_attn_mma<0> <<<dim3(N / 128, B * H), 512, SMEM_MMA_BYTES>>>(adj);
    k_gemm_dual   <<<dim3(O / 64, N / 64, B), 256>>>(W_out, W_lin, b_lin);
    k_sdots_single<<<(B * N) / 8, 256>>>(a_out);
    k_stats_single<<<B * N, 256>>>(adj);
    k_attn_mma<1> <<<dim3(N / 128, B), 512, SMEM_MMA_BYTES>>>(adj);
    k_gemm_out    <<<dim3(O / 64, (B * N) / 64), 256>>>(W_ln, b_ln, out);
}